// round 1
// baseline (speedup 1.0000x reference)
#include <cuda_runtime.h>
#include <cstdint>

// Problem constants
#define SB   1024          // sequence length S
#define DD   64            // head dim
#define BB   8             // batch
#define HH   8             // heads
#define CC   21            // dtw channels
#define QT   32            // query rows per block (kernel 2)
#define SCP  1028          // score smem pitch (floats), %32==4 -> low conflicts
#define KP   68            // K/V/Q smem pitch (floats)
#define OUT_ELEMS (BB*HH*SB*DD)   // 4194304 floats; attention starts here

// ---------------------------------------------------------------------------
// helpers
// ---------------------------------------------------------------------------
__device__ __forceinline__ unsigned f2tf(float f) {
    unsigned u;
    asm("cvt.rna.tf32.f32 %0, %1;" : "=r"(u) : "f"(f));
    return u;
}

__device__ __forceinline__ void mma_tf32(float c[4], const unsigned a[4], const unsigned b[2]) {
    asm volatile(
        "mma.sync.aligned.m16n8k8.row.col.f32.tf32.tf32.f32 "
        "{%0,%1,%2,%3}, {%4,%5,%6,%7}, {%8,%9}, {%0,%1,%2,%3};\n"
        : "+f"(c[0]), "+f"(c[1]), "+f"(c[2]), "+f"(c[3])
        : "r"(a[0]), "r"(a[1]), "r"(a[2]), "r"(a[3]), "r"(b[0]), "r"(b[1]));
}

// ---------------------------------------------------------------------------
// Kernel 1: bias[b,h,q,k] = sum_c dtw[b,c,q,k]*W[h,c] + b[h]; masked -> -1e9.
// Written into the attention region of d_out (used as scratch, later
// overwritten with the final attention). dtw read ONCE (shared across heads).
// Each thread handles 4 consecutive k (float4).
// ---------------------------------------------------------------------------
__global__ __launch_bounds__(256) void k_bias(
    const float* __restrict__ dtw, const int* __restrict__ mask,
    const float* __restrict__ W, const float* __restrict__ bvec,
    float* __restrict__ attn)   // attn = d_out + OUT_ELEMS
{
    __shared__ float Ws[HH * CC];
    __shared__ float bs[HH];
    int t = threadIdx.x;
    if (t < HH * CC) Ws[t] = W[t];
    if (t < HH)      bs[t] = bvec[t];
    __syncthreads();

    unsigned idx = blockIdx.x * 256u + (unsigned)t;   // quad index, B*S*S/4 = 2^21
    int      bb  = idx >> 18;                          // S*S/4 = 2^18
    unsigned p4  = idx & 0x3FFFFu;

    const float4* dp = reinterpret_cast<const float4*>(dtw) + (((size_t)bb * CC) << 18) + p4;
    int4 mk = reinterpret_cast<const int4*>(mask)[(((size_t)bb) << 18) + p4];

    float ax[HH], ay[HH], az[HH], aw[HH];
#pragma unroll
    for (int h = 0; h < HH; h++) { ax[h] = bs[h]; ay[h] = bs[h]; az[h] = bs[h]; aw[h] = bs[h]; }

#pragma unroll
    for (int c = 0; c < CC; c++) {
        float4 d = dp[((size_t)c) << 18];
#pragma unroll
        for (int h = 0; h < HH; h++) {
            float w = Ws[h * CC + c];
            ax[h] += w * d.x; ay[h] += w * d.y; az[h] += w * d.z; aw[h] += w * d.w;
        }
    }

    float4* ap = reinterpret_cast<float4*>(attn) + (((size_t)bb * HH) << 18) + p4;
#pragma unroll
    for (int h = 0; h < HH; h++) {
        float4 r;
        r.x = mk.x ? ax[h] : -1e9f;
        r.y = mk.y ? ay[h] : -1e9f;
        r.z = mk.z ? az[h] : -1e9f;
        r.w = mk.w ? aw[h] : -1e9f;
        ap[((size_t)h) << 18] = r;
    }
}

// ---------------------------------------------------------------------------
// Kernel 2: fused attention per (b, h, 32-query tile).
//   Phase A: Sc[32][1024] = Q * K^T via tf32 mma (K streamed in 128-row chunks)
//   Phase B: row softmax: s = Sc*0.125 + bias(gmem); write attention to gmem,
//            keep tf32(P) in Sc
//   Phase C: out[32][64] = P * V via tf32 mma (V streamed in 128-row chunks)
// smem: Sc 32*1028 + Qs 32*68 + Ks 128*68 floats = 175104 B
// ---------------------------------------------------------------------------
#define SMEM_BYTES ((QT*SCP + QT*KP + 128*KP) * 4)

extern __shared__ float smem[];

__global__ __launch_bounds__(256, 1) void k_attn(
    const float* __restrict__ Q, const float* __restrict__ K,
    const float* __restrict__ V, float* __restrict__ out)
{
    float*    Sc = smem;
    float*    Qs = smem + QT * SCP;
    float*    Ks = Qs + QT * KP;
    unsigned* Qu = reinterpret_cast<unsigned*>(Qs);
    unsigned* Ku = reinterpret_cast<unsigned*>(Ks);
    unsigned* Su = reinterpret_cast<unsigned*>(Sc);

    const int tid  = threadIdx.x;
    const int warp = tid >> 5;
    const int lane = tid & 31;
    const int g    = lane >> 2;     // groupID 0..7
    const int tg   = lane & 3;      // threadID-in-group 0..3

    const int qt = blockIdx.x & 31;        // S/QT = 32 query tiles
    const int bh = blockIdx.x >> 5;

    const float* Qg       = Q + ((size_t)bh * SB + qt * QT) * DD;
    const float* Kg       = K + (size_t)bh * SB * DD;
    const float* Vg       = V + (size_t)bh * SB * DD;
    float*       attnBase = out + OUT_ELEMS + ((size_t)bh * SB + (size_t)qt * QT) * SB;
    float*       outBase  = out + ((size_t)bh * SB + qt * QT) * DD;

    // ---- load Q tile (32x64) as tf32 ----
    for (int i = tid; i < QT * (DD / 4); i += 256) {
        int r = i >> 4, q4 = i & 15;
        float4 v = reinterpret_cast<const float4*>(Qg)[i];
        unsigned* dst = Qu + r * KP + q4 * 4;
        dst[0] = f2tf(v.x); dst[1] = f2tf(v.y); dst[2] = f2tf(v.z); dst[3] = f2tf(v.w);
    }

    // ---- Phase A: scores = Q K^T (raw, unscaled) into Sc ----
    const int nb = warp * 16;   // this warp's n-base within each 128-col chunk
    for (int ch = 0; ch < 8; ++ch) {
        __syncthreads();   // Q/Ks ready-for-reuse fence
        const float4* kg4 = reinterpret_cast<const float4*>(Kg + (size_t)ch * 128 * DD);
        for (int i = tid; i < 128 * 16; i += 256) {
            int r = i >> 4, q4 = i & 15;
            float4 v = kg4[i];
            unsigned* dst = Ku + r * KP + q4 * 4;
            dst[0] = f2tf(v.x); dst[1] = f2tf(v.y); dst[2] = f2tf(v.z); dst[3] = f2tf(v.w);
        }
        __syncthreads();

        float acc[2][2][4];
#pragma unroll
        for (int mi = 0; mi < 2; mi++)
#pragma unroll
            for (int ni = 0; ni < 2; ni++)
#pragma unroll
                for (int j = 0; j < 4; j++) acc[mi][ni][j] = 0.f;

#pragma unroll
        for (int ks = 0; ks < 8; ++ks) {
            unsigned a[2][4], bq[2][2];
#pragma unroll
            for (int mi = 0; mi < 2; mi++) {
                int row = mi * 16 + g;
                a[mi][0] = Qu[row * KP + ks * 8 + tg];
                a[mi][1] = Qu[(row + 8) * KP + ks * 8 + tg];
                a[mi][2] = Qu[row * KP + ks * 8 + tg + 4];
                a[mi][3] = Qu[(row + 8) * KP + ks * 8 + tg + 4];
            }
#pragma unroll
            for (int ni = 0; ni < 2; ni++) {
                int kkrow = nb + ni * 8 + g;
                bq[ni][0] = Ku[kkrow * KP + ks * 8 + tg];
                bq[ni][1] = Ku[kkrow * KP + ks * 8 + tg + 4];
            }
#pragma unroll
            for (int mi = 0; mi < 2; mi++)
#pragma unroll
                for (int ni = 0; ni < 2; ni++)
                    mma_tf32(acc[mi][ni], a[mi], bq[ni]);
        }

#pragma unroll
        for (int mi = 0; mi < 2; mi++)
#pragma unroll
            for (int ni = 0; ni < 2; ni++) {
                int row = mi * 16 + g;
                int col = ch * 128 + nb + ni * 8 + tg * 2;
                *reinterpret_cast<float2*>(&Sc[row * SCP + col]) =
                    make_float2(acc[mi][ni][0], acc[mi][ni][1]);
                *reinterpret_cast<float2*>(&Sc[(row + 8) * SCP + col]) =
                    make_float2(acc[mi][ni][2], acc[mi][ni][3]);
            }
    }
    __syncthreads();

    // ---- Phase B: softmax per row; bias from gmem, attention to gmem ----
    const float scale = 0.125f;   // 1/sqrt(64)
    for (int rr = 0; rr < 4; ++rr) {
        int row = warp * 4 + rr;
        float* scr = Sc + row * SCP;
        float* bg  = attnBase + (size_t)row * SB;

        float m = -3.4e38f;
        for (int n = lane; n < SB; n += 32) {
            float s = scr[n] * scale + bg[n];
            scr[n] = s;
            m = fmaxf(m, s);
        }
#pragma unroll
        for (int o = 16; o; o >>= 1) m = fmaxf(m, __shfl_xor_sync(0xffffffffu, m, o));

        float sum = 0.f;
        for (int n = lane; n < SB; n += 32) {
            float e = __expf(scr[n] - m);
            scr[n] = e;
            sum += e;
        }
#pragma unroll
        for (int o = 16; o; o >>= 1) sum += __shfl_xor_sync(0xffffffffu, sum, o);
        float rinv = 1.0f / sum;

        for (int n = lane; n < SB; n += 32) {
            float p = scr[n] * rinv;
            bg[n] = p;                                   // final attention out
            reinterpret_cast<unsigned*>(scr)[n] = f2tf(p); // tf32 P for phase C
        }
    }
    __syncthreads();

    // ---- Phase C: out = P * V ----
    float oacc[2][4];
#pragma unroll
    for (int mi = 0; mi < 2; mi++)
#pragma unroll
        for (int j = 0; j < 4; j++) oacc[mi][j] = 0.f;

    for (int ch = 0; ch < 8; ++ch) {
        __syncthreads();
        const float4* vg4 = reinterpret_cast<const float4*>(Vg + (size_t)ch * 128 * DD);
        for (int i = tid; i < 128 * 16; i += 256) {
            int r = i >> 4, q4 = i & 15;
            float4 v = vg4[i];
            unsigned* dst = Ku + r * KP + q4 * 4;
            dst[0] = f2tf(v.x); dst[1] = f2tf(v.y); dst[2] = f2tf(v.z); dst[3] = f2tf(v.w);
        }
        __syncthreads();

#pragma unroll
        for (int ks = 0; ks < 16; ++ks) {
            int kk = ch * 128 + ks * 8;
            unsigned a[2][4], bq[2];
#pragma unroll
            for (int mi = 0; mi < 2; mi++) {
                int row = mi * 16 + g;
                a[mi][0] = Su[row * SCP + kk + tg];
                a[mi][1] = Su[(row + 8) * SCP + kk + tg];
                a[mi][2] = Su[row * SCP + kk + tg + 4];
                a[mi][3] = Su[(row + 8) * SCP + kk + tg + 4];
            }
            bq[0] = Ku[(ks * 8 + tg) * KP + warp * 8 + g];
            bq[1] = Ku[(ks * 8 + tg + 4) * KP + warp * 8 + g];
            mma_tf32(oacc[0], a[0], bq);
            mma_tf32(oacc[1], a[1], bq);
        }
    }

#pragma unroll
    for (int mi = 0; mi < 2; mi++) {
        int row = mi * 16 + g;
        int col = warp * 8 + tg * 2;
        *reinterpret_cast<float2*>(outBase + (size_t)row * DD + col) =
            make_float2(oacc[mi][0], oacc[mi][1]);
        *reinterpret_cast<float2*>(outBase + (size_t)(row + 8) * DD + col) =
            make_float2(oacc[mi][2], oacc[mi][3]);
    }
}

// ---------------------------------------------------------------------------
extern "C" void kernel_launch(void* const* d_in, const int* in_sizes, int n_in,
                              void* d_out, int out_size)
{
    const float* Q    = (const float*)d_in[0];
    const float* K    = (const float*)d_in[1];
    const float* V    = (const float*)d_in[2];
    const float* dtw  = (const float*)d_in[3];
    const int*   mask = (const int*)d_in[4];
    const float* W    = (const float*)d_in[5];
    const float* bvec = (const float*)d_in[6];
    float*       out  = (float*)d_out;

    // bias into the attention region of d_out (scratch, overwritten by k_attn)
    k_bias<<<(BB * SB * SB / 4) / 256, 256>>>(dtw, mask, W, bvec, out + OUT_ELEMS);

    cudaFuncSetAttribute(k_attn, cudaFuncAttributeMaxDynamicSharedMemorySize, SMEM_BYTES);
    k_attn<<<BB * HH * (SB / QT), 256, SMEM_BYTES>>>(Q, K, V, out);
}

// round 2
// speedup vs baseline: 1.1487x; 1.1487x over previous
#include <cuda_runtime.h>
#include <cstdint>

// Problem constants
#define SB   1024          // sequence length S
#define DD   64            // head dim
#define BB   8             // batch
#define HH   8             // heads
#define CC   21            // dtw channels
#define QT   32            // query rows per block (kernel 2)
#define SCP  1028          // score smem pitch (floats), %32==4 -> low conflicts
#define KP   68            // K/V/Q smem pitch (floats)
#define NTHREADS 512
#define OUT_ELEMS (BB*HH*SB*DD)   // 4194304 floats; attention starts here

// ---------------------------------------------------------------------------
// helpers
// ---------------------------------------------------------------------------
__device__ __forceinline__ unsigned f2tf(float f) {
    unsigned u;
    asm("cvt.rna.tf32.f32 %0, %1;" : "=r"(u) : "f"(f));
    return u;
}

__device__ __forceinline__ void mma_tf32(float c[4], const unsigned a[4], const unsigned b[2]) {
    asm volatile(
        "mma.sync.aligned.m16n8k8.row.col.f32.tf32.tf32.f32 "
        "{%0,%1,%2,%3}, {%4,%5,%6,%7}, {%8,%9}, {%0,%1,%2,%3};\n"
        : "+f"(c[0]), "+f"(c[1]), "+f"(c[2]), "+f"(c[3])
        : "r"(a[0]), "r"(a[1]), "r"(a[2]), "r"(a[3]), "r"(b[0]), "r"(b[1]));
}

// ---------------------------------------------------------------------------
// Kernel 1: bias[b,h,q,k] = sum_c dtw[b,c,q,k]*W[h,c] + b[h]; masked -> -1e9.
// Written into the attention region of d_out (scratch, later overwritten).
// ---------------------------------------------------------------------------
__global__ __launch_bounds__(256) void k_bias(
    const float* __restrict__ dtw, const int* __restrict__ mask,
    const float* __restrict__ W, const float* __restrict__ bvec,
    float* __restrict__ attn)   // attn = d_out + OUT_ELEMS
{
    __shared__ float Ws[HH * CC];
    __shared__ float bs[HH];
    int t = threadIdx.x;
    if (t < HH * CC) Ws[t] = W[t];
    if (t < HH)      bs[t] = bvec[t];
    __syncthreads();

    unsigned idx = blockIdx.x * 256u + (unsigned)t;   // quad index, B*S*S/4 = 2^21
    int      bb  = idx >> 18;                          // S*S/4 = 2^18
    unsigned p4  = idx & 0x3FFFFu;

    const float4* dp = reinterpret_cast<const float4*>(dtw) + (((size_t)bb * CC) << 18) + p4;
    int4 mk = reinterpret_cast<const int4*>(mask)[(((size_t)bb) << 18) + p4];

    float ax[HH], ay[HH], az[HH], aw[HH];
#pragma unroll
    for (int h = 0; h < HH; h++) { ax[h] = bs[h]; ay[h] = bs[h]; az[h] = bs[h]; aw[h] = bs[h]; }

#pragma unroll
    for (int c = 0; c < CC; c++) {
        float4 d = dp[((size_t)c) << 18];
#pragma unroll
        for (int h = 0; h < HH; h++) {
            float w = Ws[h * CC + c];
            ax[h] += w * d.x; ay[h] += w * d.y; az[h] += w * d.z; aw[h] += w * d.w;
        }
    }

    float4* ap = reinterpret_cast<float4*>(attn) + (((size_t)bb * HH) << 18) + p4;
#pragma unroll
    for (int h = 0; h < HH; h++) {
        float4 r;
        r.x = mk.x ? ax[h] : -1e9f;
        r.y = mk.y ? ay[h] : -1e9f;
        r.z = mk.z ? az[h] : -1e9f;
        r.w = mk.w ? aw[h] : -1e9f;
        ap[((size_t)h) << 18] = r;
    }
}

// ---------------------------------------------------------------------------
// Kernel 2: fused attention per (b, h, 32-query tile). 512 threads / 16 warps.
//   Phase A: Sc[32][1024] = (Q*0.125) K^T via tf32 mma, K double-buffered
//   Phase B: softmax: s = Sc + bias(gmem); attention -> gmem, tf32 P -> Sc
//   Phase C: out[32][64] = P * V, V double-buffered
// smem: Sc 32*1028 + Qs 32*68 + 2x Kbuf 128*68 floats = 209920 B
// ---------------------------------------------------------------------------
#define SMEM_BYTES ((QT*SCP + QT*KP + 2*128*KP) * 4)

extern __shared__ float smem[];

__global__ __launch_bounds__(NTHREADS, 1) void k_attn(
    const float* __restrict__ Q, const float* __restrict__ K,
    const float* __restrict__ V, float* __restrict__ out)
{
    float*    Sc = smem;
    float*    Qs = smem + QT * SCP;
    unsigned* Qu = reinterpret_cast<unsigned*>(Qs);
    unsigned* Ku[2];
    Ku[0] = reinterpret_cast<unsigned*>(Qs + QT * KP);
    Ku[1] = Ku[0] + 128 * KP;
    unsigned* Su = reinterpret_cast<unsigned*>(Sc);

    const int tid  = threadIdx.x;
    const int warp = tid >> 5;
    const int lane = tid & 31;
    const int g    = lane >> 2;     // groupID 0..7
    const int tg   = lane & 3;      // threadID-in-group 0..3

    const int qt = blockIdx.x & 31;        // S/QT = 32 query tiles
    const int bh = blockIdx.x >> 5;

    const float* Qg       = Q + ((size_t)bh * SB + qt * QT) * DD;
    const float* Kg       = K + (size_t)bh * SB * DD;
    const float* Vg       = V + (size_t)bh * SB * DD;
    float*       attnBase = out + OUT_ELEMS + ((size_t)bh * SB + (size_t)qt * QT) * SB;
    float*       outBase  = out + ((size_t)bh * SB + qt * QT) * DD;

    // ---- load Q tile (32x64), fold 1/sqrt(64), cvt to tf32 ----
    {
        int i = tid;                    // 512 float4s, 1 per thread
        int r = i >> 4, q4 = i & 15;
        float4 v = reinterpret_cast<const float4*>(Qg)[i];
        unsigned* dst = Qu + r * KP + q4 * 4;
        dst[0] = f2tf(v.x * 0.125f); dst[1] = f2tf(v.y * 0.125f);
        dst[2] = f2tf(v.z * 0.125f); dst[3] = f2tf(v.w * 0.125f);
    }

    // ---- Phase A: scores = Qs K^T into Sc; K chunks (128 rows) double-buffered
    const int nb = warp * 8;   // this warp's n-base within each 128-col chunk
    {
        // preload chunk 0
        const float4* kg4 = reinterpret_cast<const float4*>(Kg);
#pragma unroll
        for (int j = 0; j < 4; j++) {
            int i = tid + j * NTHREADS;            // 2048 float4s per chunk
            int r = i >> 4, q4 = i & 15;
            float4 v = kg4[i];
            unsigned* dst = Ku[0] + r * KP + q4 * 4;
            dst[0] = f2tf(v.x); dst[1] = f2tf(v.y); dst[2] = f2tf(v.z); dst[3] = f2tf(v.w);
        }
        __syncthreads();

        for (int ch = 0; ch < 8; ++ch) {
            // prefetch next chunk into registers (overlaps with mma below)
            float4 pf[4];
            if (ch < 7) {
                const float4* ng4 = reinterpret_cast<const float4*>(Kg + (size_t)(ch + 1) * 128 * DD);
#pragma unroll
                for (int j = 0; j < 4; j++) pf[j] = ng4[tid + j * NTHREADS];
            }

            const unsigned* kb = Ku[ch & 1];
            float acc[2][4];
#pragma unroll
            for (int mi = 0; mi < 2; mi++)
#pragma unroll
                for (int j = 0; j < 4; j++) acc[mi][j] = 0.f;

#pragma unroll
            for (int ks = 0; ks < 8; ++ks) {
                unsigned a[2][4], bq[2];
#pragma unroll
                for (int mi = 0; mi < 2; mi++) {
                    int row = mi * 16 + g;
                    a[mi][0] = Qu[row * KP + ks * 8 + tg];
                    a[mi][1] = Qu[(row + 8) * KP + ks * 8 + tg];
                    a[mi][2] = Qu[row * KP + ks * 8 + tg + 4];
                    a[mi][3] = Qu[(row + 8) * KP + ks * 8 + tg + 4];
                }
                int kkrow = nb + g;
                bq[0] = kb[kkrow * KP + ks * 8 + tg];
                bq[1] = kb[kkrow * KP + ks * 8 + tg + 4];
                mma_tf32(acc[0], a[0], bq);
                mma_tf32(acc[1], a[1], bq);
            }

            // write scores
#pragma unroll
            for (int mi = 0; mi < 2; mi++) {
                int row = mi * 16 + g;
                int col = ch * 128 + nb + tg * 2;
                *reinterpret_cast<float2*>(&Sc[row * SCP + col]) =
                    make_float2(acc[mi][0], acc[mi][1]);
                *reinterpret_cast<float2*>(&Sc[(row + 8) * SCP + col]) =
                    make_float2(acc[mi][2], acc[mi][3]);
            }

            // store prefetched chunk into the other buffer
            if (ch < 7) {
                unsigned* dstb = Ku[(ch + 1) & 1];
#pragma unroll
                for (int j = 0; j < 4; j++) {
                    int i = tid + j * NTHREADS;
                    int r = i >> 4, q4 = i & 15;
                    unsigned* dst = dstb + r * KP + q4 * 4;
                    dst[0] = f2tf(pf[j].x); dst[1] = f2tf(pf[j].y);
                    dst[2] = f2tf(pf[j].z); dst[3] = f2tf(pf[j].w);
                }
            }
            __syncthreads();
        }
    }

    // ---- Phase B: softmax per row; bias from gmem, attention to gmem ----
#pragma unroll
    for (int rr = 0; rr < 2; ++rr) {
        int row = warp * 2 + rr;
        float* scr = Sc + row * SCP;
        float* bg  = attnBase + (size_t)row * SB;

        float m = -3.4e38f;
#pragma unroll 4
        for (int n = lane; n < SB; n += 32) {
            float s = scr[n] + bg[n];
            scr[n] = s;
            m = fmaxf(m, s);
        }
#pragma unroll
        for (int o = 16; o; o >>= 1) m = fmaxf(m, __shfl_xor_sync(0xffffffffu, m, o));

        float sum = 0.f;
#pragma unroll 4
        for (int n = lane; n < SB; n += 32) {
            float e = __expf(scr[n] - m);
            scr[n] = e;
            sum += e;
        }
#pragma unroll
        for (int o = 16; o; o >>= 1) sum += __shfl_xor_sync(0xffffffffu, sum, o);
        float rinv = 1.0f / sum;

#pragma unroll 4
        for (int n = lane; n < SB; n += 32) {
            float p = scr[n] * rinv;
            bg[n] = p;                                   // final attention out
            reinterpret_cast<unsigned*>(scr)[n] = f2tf(p); // tf32 P for phase C
        }
    }
    __syncthreads();

    // ---- Phase C: out = P * V; warp = (mi, nj) tile 16x8; V double-buffered
    const int mi = warp >> 3;         // 0..1
    const int nj = warp & 7;          // 0..7
    float oacc[4] = {0.f, 0.f, 0.f, 0.f};

    {
        const float4* vg4 = reinterpret_cast<const float4*>(Vg);
#pragma unroll
        for (int j = 0; j < 4; j++) {
            int i = tid + j * NTHREADS;
            int r = i >> 4, q4 = i & 15;
            float4 v = vg4[i];
            unsigned* dst = Ku[0] + r * KP + q4 * 4;
            dst[0] = f2tf(v.x); dst[1] = f2tf(v.y); dst[2] = f2tf(v.z); dst[3] = f2tf(v.w);
        }
        __syncthreads();

        for (int ch = 0; ch < 8; ++ch) {
            float4 pf[4];
            if (ch < 7) {
                const float4* ng4 = reinterpret_cast<const float4*>(Vg + (size_t)(ch + 1) * 128 * DD);
#pragma unroll
                for (int j = 0; j < 4; j++) pf[j] = ng4[tid + j * NTHREADS];
            }

            const unsigned* vb = Ku[ch & 1];
#pragma unroll
            for (int ks = 0; ks < 16; ++ks) {
                int kk = ch * 128 + ks * 8;
                unsigned a[4], bq[2];
                int row = mi * 16 + g;
                a[0] = Su[row * SCP + kk + tg];
                a[1] = Su[(row + 8) * SCP + kk + tg];
                a[2] = Su[row * SCP + kk + tg + 4];
                a[3] = Su[(row + 8) * SCP + kk + tg + 4];
                bq[0] = vb[(ks * 8 + tg) * KP + nj * 8 + g];
                bq[1] = vb[(ks * 8 + tg + 4) * KP + nj * 8 + g];
                mma_tf32(oacc, a, bq);
            }

            if (ch < 7) {
                unsigned* dstb = Ku[(ch + 1) & 1];
#pragma unroll
                for (int j = 0; j < 4; j++) {
                    int i = tid + j * NTHREADS;
                    int r = i >> 4, q4 = i & 15;
                    unsigned* dst = dstb + r * KP + q4 * 4;
                    dst[0] = f2tf(pf[j].x); dst[1] = f2tf(pf[j].y);
                    dst[2] = f2tf(pf[j].z); dst[3] = f2tf(pf[j].w);
                }
            }
            __syncthreads();
        }
    }

    {
        int row = mi * 16 + g;
        int col = nj * 8 + tg * 2;
        *reinterpret_cast<float2*>(outBase + (size_t)row * DD + col) =
            make_float2(oacc[0], oacc[1]);
        *reinterpret_cast<float2*>(outBase + (size_t)(row + 8) * DD + col) =
            make_float2(oacc[2], oacc[3]);
    }
}

// ---------------------------------------------------------------------------
extern "C" void kernel_launch(void* const* d_in, const int* in_sizes, int n_in,
                              void* d_out, int out_size)
{
    const float* Q    = (const float*)d_in[0];
    const float* K    = (const float*)d_in[1];
    const float* V    = (const float*)d_in[2];
    const float* dtw  = (const float*)d_in[3];
    const int*   mask = (const int*)d_in[4];
    const float* W    = (const float*)d_in[5];
    const float* bvec = (const float*)d_in[6];
    float*       out  = (float*)d_out;

    // bias into the attention region of d_out (scratch, overwritten by k_attn)
    k_bias<<<(BB * SB * SB / 4) / 256, 256>>>(dtw, mask, W, bvec, out + OUT_ELEMS);

    cudaFuncSetAttribute(k_attn, cudaFuncAttributeMaxDynamicSharedMemorySize, SMEM_BYTES);
    k_attn<<<BB * HH * (SB / QT), NTHREADS, SMEM_BYTES>>>(Q, K, V, out);
}

// round 3
// speedup vs baseline: 1.5379x; 1.3388x over previous
#include <cuda_runtime.h>
#include <cuda_fp16.h>
#include <cstdint>

// Problem constants
#define SB   1024          // sequence length S
#define DD   64            // head dim
#define BB   8             // batch
#define HH   8             // heads
#define CC   21            // dtw channels
#define QT   32            // query rows per block (kernel 2)
#define SCP  1028          // score smem pitch (floats / uint-pairs)
#define KPU  36            // K/Q smem pitch in uints (72 halves)
#define VPU  133           // V^T smem pitch in uints (266 halves)
#define VPH  266
#define CHK  256           // K/V rows per chunk
#define NTHREADS 512
#define OUT_ELEMS (BB*HH*SB*DD)   // attention starts here in d_out

// ---------------------------------------------------------------------------
__device__ __forceinline__ unsigned packh2(float x, float y) {
    __half2 h = __float22half2_rn(make_float2(x, y));
    return *reinterpret_cast<unsigned*>(&h);
}

__device__ __forceinline__ void mma_f16(float c[4], const unsigned a[4], const unsigned b[2]) {
    asm volatile(
        "mma.sync.aligned.m16n8k16.row.col.f32.f16.f16.f32 "
        "{%0,%1,%2,%3}, {%4,%5,%6,%7}, {%8,%9}, {%0,%1,%2,%3};\n"
        : "+f"(c[0]), "+f"(c[1]), "+f"(c[2]), "+f"(c[3])
        : "r"(a[0]), "r"(a[1]), "r"(a[2]), "r"(a[3]), "r"(b[0]), "r"(b[1]));
}

// ---------------------------------------------------------------------------
// Kernel 1: bias[b,h,q,k] = sum_c dtw[b,c,q,k]*W[h,c] + b[h]; masked -> -1e9.
// Written into attention region of d_out (scratch).
// ---------------------------------------------------------------------------
__global__ __launch_bounds__(256) void k_bias(
    const float* __restrict__ dtw, const int* __restrict__ mask,
    const float* __restrict__ W, const float* __restrict__ bvec,
    float* __restrict__ attn)
{
    __shared__ float Ws[HH * CC];
    __shared__ float bs[HH];
    int t = threadIdx.x;
    if (t < HH * CC) Ws[t] = W[t];
    if (t < HH)      bs[t] = bvec[t];
    __syncthreads();

    unsigned idx = blockIdx.x * 256u + (unsigned)t;
    int      bb  = idx >> 18;
    unsigned p4  = idx & 0x3FFFFu;

    const float4* dp = reinterpret_cast<const float4*>(dtw) + (((size_t)bb * CC) << 18) + p4;
    int4 mk = reinterpret_cast<const int4*>(mask)[(((size_t)bb) << 18) + p4];

    float ax[HH], ay[HH], az[HH], aw[HH];
#pragma unroll
    for (int h = 0; h < HH; h++) { ax[h] = bs[h]; ay[h] = bs[h]; az[h] = bs[h]; aw[h] = bs[h]; }

#pragma unroll
    for (int c = 0; c < CC; c++) {
        float4 d = dp[((size_t)c) << 18];
#pragma unroll
        for (int h = 0; h < HH; h++) {
            float w = Ws[h * CC + c];
            ax[h] += w * d.x; ay[h] += w * d.y; az[h] += w * d.z; aw[h] += w * d.w;
        }
    }

    float4* ap = reinterpret_cast<float4*>(attn) + (((size_t)bb * HH) << 18) + p4;
#pragma unroll
    for (int h = 0; h < HH; h++) {
        float4 r;
        r.x = mk.x ? ax[h] : -1e9f;
        r.y = mk.y ? ay[h] : -1e9f;
        r.z = mk.z ? az[h] : -1e9f;
        r.w = mk.w ? aw[h] : -1e9f;
        ap[((size_t)h) << 18] = r;
    }
}

// ---------------------------------------------------------------------------
// Kernel 2: fused attention, fp16 mma m16n8k16. 512 threads / 16 warps.
// smem: Sc fp32 32x1028 | Q fp16 32x72 | 2x chunk buf (K fp16 256x72 / V^T fp16 64x266)
//  = (32*1028 + 32*36 + 2*256*36) uints = 52480 uints = 209920 B
// ---------------------------------------------------------------------------
#define SMEM_UINTS (QT*SCP + QT*KPU + 2*CHK*KPU)
#define SMEM_BYTES (SMEM_UINTS * 4)

extern __shared__ float smem[];

__global__ __launch_bounds__(NTHREADS, 1) void k_attn(
    const float* __restrict__ Q, const float* __restrict__ K,
    const float* __restrict__ V, float* __restrict__ out)
{
    float*    Sc = smem;
    unsigned* Su = reinterpret_cast<unsigned*>(Sc);     // pair view (pitch SCP uints)
    unsigned* Qu = reinterpret_cast<unsigned*>(smem + QT * SCP);
    unsigned* Kb[2];
    Kb[0] = Qu + QT * KPU;
    Kb[1] = Kb[0] + CHK * KPU;

    const int tid  = threadIdx.x;
    const int warp = tid >> 5;
    const int lane = tid & 31;
    const int g    = lane >> 2;
    const int tg   = lane & 3;

    const int qt = blockIdx.x & 31;
    const int bh = blockIdx.x >> 5;

    const float* Qg       = Q + ((size_t)bh * SB + qt * QT) * DD;
    const float* Kg       = K + (size_t)bh * SB * DD;
    const float* Vg       = V + (size_t)bh * SB * DD;
    float*       attnBase = out + OUT_ELEMS + ((size_t)bh * SB + (size_t)qt * QT) * SB;
    float*       outBase  = out + ((size_t)bh * SB + qt * QT) * DD;

    // ---- load Q tile (32x64), fold 1/8, cvt fp16 ----
    {
        int i = tid;                           // 512 float4s
        int r = i >> 4, c2 = (i & 15) * 2;
        float4 v = reinterpret_cast<const float4*>(Qg)[i];
        unsigned* dst = Qu + r * KPU + c2;
        dst[0] = packh2(v.x * 0.125f, v.y * 0.125f);
        dst[1] = packh2(v.z * 0.125f, v.w * 0.125f);
    }

    // ---- Phase A: scores = Q K^T; 4 chunks of 256 K-rows, double-buffered ----
    const int wn = warp * 16;     // warp's n-base within chunk
    {
        const float4* kg4 = reinterpret_cast<const float4*>(Kg);
#pragma unroll
        for (int j = 0; j < 8; j++) {          // 4096 float4 per chunk
            int i = tid + j * NTHREADS;
            int r = i >> 4, c2 = (i & 15) * 2;
            float4 v = kg4[i];
            unsigned* dst = Kb[0] + r * KPU + c2;
            dst[0] = packh2(v.x, v.y);
            dst[1] = packh2(v.z, v.w);
        }
        __syncthreads();

        for (int ch = 0; ch < 4; ++ch) {
            float4 pf[8];
            if (ch < 3) {
                const float4* ng4 = reinterpret_cast<const float4*>(Kg + (size_t)(ch + 1) * CHK * DD);
#pragma unroll
                for (int j = 0; j < 8; j++) pf[j] = ng4[tid + j * NTHREADS];
            }

            const unsigned* kb = Kb[ch & 1];
            float acc[2][2][4];
#pragma unroll
            for (int mi = 0; mi < 2; mi++)
#pragma unroll
                for (int ni = 0; ni < 2; ni++)
#pragma unroll
                    for (int j = 0; j < 4; j++) acc[mi][ni][j] = 0.f;

#pragma unroll
            for (int ks = 0; ks < 4; ++ks) {   // k16 steps over D=64
                int ku = ks * 8;               // uint offset
                unsigned a[2][4], bq[2][2];
#pragma unroll
                for (int mi = 0; mi < 2; mi++) {
                    int row = mi * 16 + g;
                    a[mi][0] = Qu[row * KPU + ku + tg];
                    a[mi][1] = Qu[(row + 8) * KPU + ku + tg];
                    a[mi][2] = Qu[row * KPU + ku + tg + 4];
                    a[mi][3] = Qu[(row + 8) * KPU + ku + tg + 4];
                }
#pragma unroll
                for (int ni = 0; ni < 2; ni++) {
                    int n = wn + ni * 8 + g;
                    bq[ni][0] = kb[n * KPU + ku + tg];
                    bq[ni][1] = kb[n * KPU + ku + tg + 4];
                }
#pragma unroll
                for (int mi = 0; mi < 2; mi++)
#pragma unroll
                    for (int ni = 0; ni < 2; ni++)
                        mma_f16(acc[mi][ni], a[mi], bq[ni]);
            }

#pragma unroll
            for (int mi = 0; mi < 2; mi++)
#pragma unroll
                for (int ni = 0; ni < 2; ni++) {
                    int row = mi * 16 + g;
                    int col = ch * CHK + wn + ni * 8 + tg * 2;
                    *reinterpret_cast<float2*>(&Sc[row * SCP + col]) =
                        make_float2(acc[mi][ni][0], acc[mi][ni][1]);
                    *reinterpret_cast<float2*>(&Sc[(row + 8) * SCP + col]) =
                        make_float2(acc[mi][ni][2], acc[mi][ni][3]);
                }

            if (ch < 3) {
                unsigned* dstb = Kb[(ch + 1) & 1];
#pragma unroll
                for (int j = 0; j < 8; j++) {
                    int i = tid + j * NTHREADS;
                    int r = i >> 4, c2 = (i & 15) * 2;
                    unsigned* dst = dstb + r * KPU + c2;
                    dst[0] = packh2(pf[j].x, pf[j].y);
                    dst[1] = packh2(pf[j].z, pf[j].w);
                }
            }
            __syncthreads();
        }
    }

    // ---- Phase B: softmax; bias from gmem; attention->gmem; packed fp16 P into Sc
#pragma unroll
    for (int rr = 0; rr < 2; ++rr) {
        int row = warp * 2 + rr;
        float*    scr = Sc + row * SCP;
        unsigned* spu = Su + row * SCP;
        float*    bg  = attnBase + (size_t)row * SB;

        float m = -3.4e38f;
#pragma unroll 4
        for (int n = lane; n < SB; n += 32) {
            float s = scr[n] + bg[n];
            scr[n] = s;
            m = fmaxf(m, s);
        }
#pragma unroll
        for (int o = 16; o; o >>= 1) m = fmaxf(m, __shfl_xor_sync(0xffffffffu, m, o));

        float sum = 0.f;
#pragma unroll 4
        for (int n = lane; n < SB; n += 32) {
            float e = __expf(scr[n] - m);
            scr[n] = e;
            sum += e;
        }
#pragma unroll
        for (int o = 16; o; o >>= 1) sum += __shfl_xor_sync(0xffffffffu, sum, o);
        float rinv = 1.0f / sum;

        // normalize: write fp32 attention to gmem, pack half2 pairs into Sc in place.
        // pair slot j (<= 2j) is only written after slots 2j,2j+1 were read (in-warp order).
        for (int j = lane; j < SB / 2; j += 32) {
            float p0 = scr[2 * j]     * rinv;
            float p1 = scr[2 * j + 1] * rinv;
            *reinterpret_cast<float2*>(bg + 2 * j) = make_float2(p0, p1);
            spu[j] = packh2(p0, p1);
        }
    }
    __syncthreads();

    // ---- Phase C: out = P * V; V chunks 256 rows, stored transposed fp16 ----
    const int mi = warp >> 3;         // 0..1
    const int nj = warp & 7;          // 0..7
    float oacc[4] = {0.f, 0.f, 0.f, 0.f};

    {
        // load V chunk 0 transposed
        const float4* vg4 = reinterpret_cast<const float4*>(Vg);
        {
            __half* vh = reinterpret_cast<__half*>(Kb[0]);
#pragma unroll
            for (int j = 0; j < 8; j++) {
                int i = tid + j * NTHREADS;
                int r = i >> 4, d0 = (i & 15) * 4;
                float4 v = vg4[i];
                vh[(d0 + 0) * VPH + r] = __float2half_rn(v.x);
                vh[(d0 + 1) * VPH + r] = __float2half_rn(v.y);
                vh[(d0 + 2) * VPH + r] = __float2half_rn(v.z);
                vh[(d0 + 3) * VPH + r] = __float2half_rn(v.w);
            }
        }
        __syncthreads();

        for (int ch = 0; ch < 4; ++ch) {
            float4 pf[8];
            if (ch < 3) {
                const float4* ng4 = reinterpret_cast<const float4*>(Vg + (size_t)(ch + 1) * CHK * DD);
#pragma unroll
                for (int j = 0; j < 8; j++) pf[j] = ng4[tid + j * NTHREADS];
            }

            const unsigned* vu = Kb[ch & 1];
            const int row  = mi * 16 + g;
            const int vrow = (nj * 8 + g) * VPU;
#pragma unroll
            for (int ks = 0; ks < 16; ++ks) {       // k16 steps over 256 chunk rows
                int ku = ch * 128 + ks * 8;          // global pair offset into Sc
                unsigned a[4], bq[2];
                a[0] = Su[row * SCP + ku + tg];
                a[1] = Su[(row + 8) * SCP + ku + tg];
                a[2] = Su[row * SCP + ku + tg + 4];
                a[3] = Su[(row + 8) * SCP + ku + tg + 4];
                bq[0] = vu[vrow + ks * 8 + tg];
                bq[1] = vu[vrow + ks * 8 + tg + 4];
                mma_f16(oacc, a, bq);
            }

            if (ch < 3) {
                __half* vh = reinterpret_cast<__half*>(Kb[(ch + 1) & 1]);
#pragma unroll
                for (int j = 0; j < 8; j++) {
                    int i = tid + j * NTHREADS;
                    int r = i >> 4, d0 = (i & 15) * 4;
                    vh[(d0 + 0) * VPH + r] = __float2half_rn(pf[j].x);
                    vh[(d0 + 1) * VPH + r] = __float2half_rn(pf[j].y);
                    vh[(d0 + 2) * VPH + r] = __float2half_rn(pf[j].z);
                    vh[(d0 + 3) * VPH + r] = __float2half_rn(pf[j].w);
                }
            }
            __syncthreads();
        }
    }

    {
        int row = mi * 16 + g;
        int col = nj * 8 + tg * 2;
        *reinterpret_cast<float2*>(outBase + (size_t)row * DD + col) =
            make_float2(oacc[0], oacc[1]);
        *reinterpret_cast<float2*>(outBase + (size_t)(row + 8) * DD + col) =
            make_float2(oacc[2], oacc[3]);
    }
}

// ---------------------------------------------------------------------------
extern "C" void kernel_launch(void* const* d_in, const int* in_sizes, int n_in,
                              void* d_out, int out_size)
{
    const float* Q    = (const float*)d_in[0];
    const float* K    = (const float*)d_in[1];
    const float* V    = (const float*)d_in[2];
    const float* dtw  = (const float*)d_in[3];
    const int*   mask = (const int*)d_in[4];
    const float* W    = (const float*)d_in[5];
    const float* bvec = (const float*)d_in[6];
    float*       out  = (float*)d_out;

    k_bias<<<(BB * SB * SB / 4) / 256, 256>>>(dtw, mask, W, bvec, out + OUT_ELEMS);

    cudaFuncSetAttribute(k_attn, cudaFuncAttributeMaxDynamicSharedMemorySize, SMEM_BYTES);
    k_attn<<<BB * HH * (SB / QT), NTHREADS, SMEM_BYTES>>>(Q, K, V, out);
}

// round 4
// speedup vs baseline: 1.5392x; 1.0009x over previous
#include <cuda_runtime.h>
#include <cuda_fp16.h>
#include <cstdint>

// Problem constants
#define SB   1024          // sequence length S
#define DD   64            // head dim
#define BB   8             // batch
#define HH   8             // heads
#define CC   21            // dtw channels
#define QT   32            // query rows per block (kernel 2)
#define SCP  1028          // score smem pitch (floats / uint-pairs)
#define KPU  36            // K/Q smem pitch in uints (72 halves)
#define VPU  133           // V^T smem pitch in uints (266 halves)
#define VPH  266
#define CHK  256           // K/V rows per chunk
#define NTHREADS 512
#define OUT_ELEMS (BB*HH*SB*DD)   // attention starts here in d_out

// ---------------------------------------------------------------------------
__device__ __forceinline__ unsigned packh2(float x, float y) {
    __half2 h = __float22half2_rn(make_float2(x, y));
    return *reinterpret_cast<unsigned*>(&h);
}

__device__ __forceinline__ void mma_f16(float c[4], const unsigned a[4], const unsigned b[2]) {
    asm volatile(
        "mma.sync.aligned.m16n8k16.row.col.f32.f16.f16.f32 "
        "{%0,%1,%2,%3}, {%4,%5,%6,%7}, {%8,%9}, {%0,%1,%2,%3};\n"
        : "+f"(c[0]), "+f"(c[1]), "+f"(c[2]), "+f"(c[3])
        : "r"(a[0]), "r"(a[1]), "r"(a[2]), "r"(a[3]), "r"(b[0]), "r"(b[1]));
}

// ---------------------------------------------------------------------------
// Kernel 1: bias[b,h,q,k] = sum_c dtw[b,c,q,k]*W[h,c] + b[h]; masked -> -1e9.
// Written into attention region of d_out (scratch).
// ---------------------------------------------------------------------------
__global__ __launch_bounds__(256) void k_bias(
    const float* __restrict__ dtw, const int* __restrict__ mask,
    const float* __restrict__ W, const float* __restrict__ bvec,
    float* __restrict__ attn)
{
    __shared__ float Ws[HH * CC];
    __shared__ float bs[HH];
    int t = threadIdx.x;
    if (t < HH * CC) Ws[t] = W[t];
    if (t < HH)      bs[t] = bvec[t];
    __syncthreads();

    unsigned idx = blockIdx.x * 256u + (unsigned)t;
    int      bb  = idx >> 18;
    unsigned p4  = idx & 0x3FFFFu;

    const float4* dp = reinterpret_cast<const float4*>(dtw) + (((size_t)bb * CC) << 18) + p4;
    int4 mk = reinterpret_cast<const int4*>(mask)[(((size_t)bb) << 18) + p4];

    float ax[HH], ay[HH], az[HH], aw[HH];
#pragma unroll
    for (int h = 0; h < HH; h++) { ax[h] = bs[h]; ay[h] = bs[h]; az[h] = bs[h]; aw[h] = bs[h]; }

#pragma unroll
    for (int c = 0; c < CC; c++) {
        float4 d = dp[((size_t)c) << 18];
#pragma unroll
        for (int h = 0; h < HH; h++) {
            float w = Ws[h * CC + c];
            ax[h] += w * d.x; ay[h] += w * d.y; az[h] += w * d.z; aw[h] += w * d.w;
        }
    }

    float4* ap = reinterpret_cast<float4*>(attn) + (((size_t)bb * HH) << 18) + p4;
#pragma unroll
    for (int h = 0; h < HH; h++) {
        float4 r;
        r.x = mk.x ? ax[h] : -1e9f;
        r.y = mk.y ? ay[h] : -1e9f;
        r.z = mk.z ? az[h] : -1e9f;
        r.w = mk.w ? aw[h] : -1e9f;
        ap[((size_t)h) << 18] = r;
    }
}

// ---------------------------------------------------------------------------
// Kernel 2: fused attention, fp16 mma m16n8k16. 512 threads / 16 warps.
// smem: Sc fp32 32x1028 | Q fp16 32x72 | 2x chunk buf (K fp16 256x72 / V^T fp16 64x266)
//  = (32*1028 + 32*36 + 2*256*36) uints = 52480 uints = 209920 B
// ---------------------------------------------------------------------------
#define SMEM_UINTS (QT*SCP + QT*KPU + 2*CHK*KPU)
#define SMEM_BYTES (SMEM_UINTS * 4)

extern __shared__ float smem[];

__global__ __launch_bounds__(NTHREADS, 1) void k_attn(
    const float* __restrict__ Q, const float* __restrict__ K,
    const float* __restrict__ V, float* __restrict__ out)
{
    float*    Sc = smem;
    unsigned* Su = reinterpret_cast<unsigned*>(Sc);     // pair view (pitch SCP uints)
    unsigned* Qu = reinterpret_cast<unsigned*>(smem + QT * SCP);
    unsigned* Kb[2];
    Kb[0] = Qu + QT * KPU;
    Kb[1] = Kb[0] + CHK * KPU;

    const int tid  = threadIdx.x;
    const int warp = tid >> 5;
    const int lane = tid & 31;
    const int g    = lane >> 2;
    const int tg   = lane & 3;

    const int qt = blockIdx.x & 31;
    const int bh = blockIdx.x >> 5;

    const float* Qg       = Q + ((size_t)bh * SB + qt * QT) * DD;
    const float* Kg       = K + (size_t)bh * SB * DD;
    const float* Vg       = V + (size_t)bh * SB * DD;
    float*       attnBase = out + OUT_ELEMS + ((size_t)bh * SB + (size_t)qt * QT) * SB;
    float*       outBase  = out + ((size_t)bh * SB + qt * QT) * DD;

    // ---- load Q tile (32x64), fold 1/8, cvt fp16 ----
    {
        int i = tid;                           // 512 float4s
        int r = i >> 4, c2 = (i & 15) * 2;
        float4 v = reinterpret_cast<const float4*>(Qg)[i];
        unsigned* dst = Qu + r * KPU + c2;
        dst[0] = packh2(v.x * 0.125f, v.y * 0.125f);
        dst[1] = packh2(v.z * 0.125f, v.w * 0.125f);
    }

    // ---- Phase A: scores = Q K^T; 4 chunks of 256 K-rows, double-buffered ----
    const int wn = warp * 16;     // warp's n-base within chunk
    {
        const float4* kg4 = reinterpret_cast<const float4*>(Kg);
#pragma unroll
        for (int j = 0; j < 8; j++) {          // 4096 float4 per chunk
            int i = tid + j * NTHREADS;
            int r = i >> 4, c2 = (i & 15) * 2;
            float4 v = kg4[i];
            unsigned* dst = Kb[0] + r * KPU + c2;
            dst[0] = packh2(v.x, v.y);
            dst[1] = packh2(v.z, v.w);
        }
        __syncthreads();

        for (int ch = 0; ch < 4; ++ch) {
            float4 pf[8];
            if (ch < 3) {
                const float4* ng4 = reinterpret_cast<const float4*>(Kg + (size_t)(ch + 1) * CHK * DD);
#pragma unroll
                for (int j = 0; j < 8; j++) pf[j] = ng4[tid + j * NTHREADS];
            }

            const unsigned* kb = Kb[ch & 1];
            float acc[2][2][4];
#pragma unroll
            for (int mi = 0; mi < 2; mi++)
#pragma unroll
                for (int ni = 0; ni < 2; ni++)
#pragma unroll
                    for (int j = 0; j < 4; j++) acc[mi][ni][j] = 0.f;

#pragma unroll
            for (int ks = 0; ks < 4; ++ks) {   // k16 steps over D=64
                int ku = ks * 8;               // uint offset
                unsigned a[2][4], bq[2][2];
#pragma unroll
                for (int mi = 0; mi < 2; mi++) {
                    int row = mi * 16 + g;
                    a[mi][0] = Qu[row * KPU + ku + tg];
                    a[mi][1] = Qu[(row + 8) * KPU + ku + tg];
                    a[mi][2] = Qu[row * KPU + ku + tg + 4];
                    a[mi][3] = Qu[(row + 8) * KPU + ku + tg + 4];
                }
#pragma unroll
                for (int ni = 0; ni < 2; ni++) {
                    int n = wn + ni * 8 + g;
                    bq[ni][0] = kb[n * KPU + ku + tg];
                    bq[ni][1] = kb[n * KPU + ku + tg + 4];
                }
#pragma unroll
                for (int mi = 0; mi < 2; mi++)
#pragma unroll
                    for (int ni = 0; ni < 2; ni++)
                        mma_f16(acc[mi][ni], a[mi], bq[ni]);
            }

#pragma unroll
            for (int mi = 0; mi < 2; mi++)
#pragma unroll
                for (int ni = 0; ni < 2; ni++) {
                    int row = mi * 16 + g;
                    int col = ch * CHK + wn + ni * 8 + tg * 2;
                    *reinterpret_cast<float2*>(&Sc[row * SCP + col]) =
                        make_float2(acc[mi][ni][0], acc[mi][ni][1]);
                    *reinterpret_cast<float2*>(&Sc[(row + 8) * SCP + col]) =
                        make_float2(acc[mi][ni][2], acc[mi][ni][3]);
                }

            if (ch < 3) {
                unsigned* dstb = Kb[(ch + 1) & 1];
#pragma unroll
                for (int j = 0; j < 8; j++) {
                    int i = tid + j * NTHREADS;
                    int r = i >> 4, c2 = (i & 15) * 2;
                    unsigned* dst = dstb + r * KPU + c2;
                    dst[0] = packh2(pf[j].x, pf[j].y);
                    dst[1] = packh2(pf[j].z, pf[j].w);
                }
            }
            __syncthreads();
        }
    }

    // ---- Phase B: softmax; bias from gmem; attention->gmem; packed fp16 P into Sc
#pragma unroll
    for (int rr = 0; rr < 2; ++rr) {
        int row = warp * 2 + rr;
        float*    scr = Sc + row * SCP;
        unsigned* spu = Su + row * SCP;
        float*    bg  = attnBase + (size_t)row * SB;

        float m = -3.4e38f;
#pragma unroll 4
        for (int n = lane; n < SB; n += 32) {
            float s = scr[n] + bg[n];
            scr[n] = s;
            m = fmaxf(m, s);
        }
#pragma unroll
        for (int o = 16; o; o >>= 1) m = fmaxf(m, __shfl_xor_sync(0xffffffffu, m, o));

        float sum = 0.f;
#pragma unroll 4
        for (int n = lane; n < SB; n += 32) {
            float e = __expf(scr[n] - m);
            scr[n] = e;
            sum += e;
        }
#pragma unroll
        for (int o = 16; o; o >>= 1) sum += __shfl_xor_sync(0xffffffffu, sum, o);
        float rinv = 1.0f / sum;

        // normalize: write fp32 attention to gmem, pack half2 pairs into Sc in place.
        // pair slot j (<= 2j) is only written after slots 2j,2j+1 were read (in-warp order).
        for (int j = lane; j < SB / 2; j += 32) {
            float p0 = scr[2 * j]     * rinv;
            float p1 = scr[2 * j + 1] * rinv;
            *reinterpret_cast<float2*>(bg + 2 * j) = make_float2(p0, p1);
            spu[j] = packh2(p0, p1);
        }
    }
    __syncthreads();

    // ---- Phase C: out = P * V; V chunks 256 rows, stored transposed fp16 ----
    const int mi = warp >> 3;         // 0..1
    const int nj = warp & 7;          // 0..7
    float oacc[4] = {0.f, 0.f, 0.f, 0.f};

    {
        // load V chunk 0 transposed
        const float4* vg4 = reinterpret_cast<const float4*>(Vg);
        {
            __half* vh = reinterpret_cast<__half*>(Kb[0]);
#pragma unroll
            for (int j = 0; j < 8; j++) {
                int i = tid + j * NTHREADS;
                int r = i >> 4, d0 = (i & 15) * 4;
                float4 v = vg4[i];
                vh[(d0 + 0) * VPH + r] = __float2half_rn(v.x);
                vh[(d0 + 1) * VPH + r] = __float2half_rn(v.y);
                vh[(d0 + 2) * VPH + r] = __float2half_rn(v.z);
                vh[(d0 + 3) * VPH + r] = __float2half_rn(v.w);
            }
        }
        __syncthreads();

        for (int ch = 0; ch < 4; ++ch) {
            float4 pf[8];
            if (ch < 3) {
                const float4* ng4 = reinterpret_cast<const float4*>(Vg + (size_t)(ch + 1) * CHK * DD);
#pragma unroll
                for (int j = 0; j < 8; j++) pf[j] = ng4[tid + j * NTHREADS];
            }

            const unsigned* vu = Kb[ch & 1];
            const int row  = mi * 16 + g;
            const int vrow = (nj * 8 + g) * VPU;
#pragma unroll
            for (int ks = 0; ks < 16; ++ks) {       // k16 steps over 256 chunk rows
                int ku = ch * 128 + ks * 8;          // global pair offset into Sc
                unsigned a[4], bq[2];
                a[0] = Su[row * SCP + ku + tg];
                a[1] = Su[(row + 8) * SCP + ku + tg];
                a[2] = Su[row * SCP + ku + tg + 4];
                a[3] = Su[(row + 8) * SCP + ku + tg + 4];
                bq[0] = vu[vrow + ks * 8 + tg];
                bq[1] = vu[vrow + ks * 8 + tg + 4];
                mma_f16(oacc, a, bq);
            }

            if (ch < 3) {
                __half* vh = reinterpret_cast<__half*>(Kb[(ch + 1) & 1]);
#pragma unroll
                for (int j = 0; j < 8; j++) {
                    int i = tid + j * NTHREADS;
                    int r = i >> 4, d0 = (i & 15) * 4;
                    vh[(d0 + 0) * VPH + r] = __float2half_rn(pf[j].x);
                    vh[(d0 + 1) * VPH + r] = __float2half_rn(pf[j].y);
                    vh[(d0 + 2) * VPH + r] = __float2half_rn(pf[j].z);
                    vh[(d0 + 3) * VPH + r] = __float2half_rn(pf[j].w);
                }
            }
            __syncthreads();
        }
    }

    {
        int row = mi * 16 + g;
        int col = nj * 8 + tg * 2;
        *reinterpret_cast<float2*>(outBase + (size_t)row * DD + col) =
            make_float2(oacc[0], oacc[1]);
        *reinterpret_cast<float2*>(outBase + (size_t)(row + 8) * DD + col) =
            make_float2(oacc[2], oacc[3]);
    }
}

// ---------------------------------------------------------------------------
extern "C" void kernel_launch(void* const* d_in, const int* in_sizes, int n_in,
                              void* d_out, int out_size)
{
    const float* Q    = (const float*)d_in[0];
    const float* K    = (const float*)d_in[1];
    const float* V    = (const float*)d_in[2];
    const float* dtw  = (const float*)d_in[3];
    const int*   mask = (const int*)d_in[4];
    const float* W    = (const float*)d_in[5];
    const float* bvec = (const float*)d_in[6];
    float*       out  = (float*)d_out;

    k_bias<<<(BB * SB * SB / 4) / 256, 256>>>(dtw, mask, W, bvec, out + OUT_ELEMS);

    cudaFuncSetAttribute(k_attn, cudaFuncAttributeMaxDynamicSharedMemorySize, SMEM_BYTES);
    k_attn<<<BB * HH * (SB / QT), NTHREADS, SMEM_BYTES>>>(Q, K, V, out);
}

// round 5
// speedup vs baseline: 1.8890x; 1.2272x over previous
#include <cuda_runtime.h>
#include <cuda_fp16.h>
#include <cstdint>

// Problem constants
#define SB   1024
#define DD   64
#define BB   8
#define HH   8
#define CC   21
#define OUT_ELEMS (BB*HH*SB*DD)   // 4194304 floats; attention region follows
#define KPU  36                   // smem row pitch in uints (72 halves) -> conflict-free
#define VPH  72                   // Vt pitch in halves

// ---------------------------------------------------------------------------
__device__ __forceinline__ unsigned packh2(float x, float y) {
    __half2 h = __float22half2_rn(make_float2(x, y));
    return *reinterpret_cast<unsigned*>(&h);
}

__device__ __forceinline__ void mma_f16(float c[4], const unsigned a[4],
                                        unsigned b0, unsigned b1) {
    asm volatile(
        "mma.sync.aligned.m16n8k16.row.col.f32.f16.f16.f32 "
        "{%0,%1,%2,%3}, {%4,%5,%6,%7}, {%8,%9}, {%0,%1,%2,%3};\n"
        : "+f"(c[0]), "+f"(c[1]), "+f"(c[2]), "+f"(c[3])
        : "r"(a[0]), "r"(a[1]), "r"(a[2]), "r"(a[3]), "r"(b0), "r"(b1));
}

// ---------------------------------------------------------------------------
// Kernel 1: bias[b,h,q,k] = sum_c dtw[b,c,q,k]*W[h,c] + b[h]; masked -> -60000.
// Stored as fp16 in the UPPER HALF (byte offsets [2048,4096)) of each
// attention row of d_out. k_attn2 consumes it and overwrites the row with the
// final fp32 attention.
// ---------------------------------------------------------------------------
__global__ __launch_bounds__(256) void k_bias(
    const float* __restrict__ dtw, const int* __restrict__ mask,
    const float* __restrict__ W, const float* __restrict__ bvec,
    float* __restrict__ attn)
{
    __shared__ float Ws[HH * CC];
    __shared__ float bs[HH];
    int t = threadIdx.x;
    if (t < HH * CC) Ws[t] = W[t];
    if (t < HH)      bs[t] = bvec[t];
    __syncthreads();

    unsigned idx = blockIdx.x * 256u + (unsigned)t;   // quad index over B*S*S/4
    int      bb  = idx >> 18;
    unsigned p4  = idx & 0x3FFFFu;

    const float4* dp = reinterpret_cast<const float4*>(dtw) + (((size_t)bb * CC) << 18) + p4;
    int4 mk = reinterpret_cast<const int4*>(mask)[(((size_t)bb) << 18) + p4];

    float ax[HH], ay[HH], az[HH], aw[HH];
#pragma unroll
    for (int h = 0; h < HH; h++) { ax[h] = bs[h]; ay[h] = bs[h]; az[h] = bs[h]; aw[h] = bs[h]; }

#pragma unroll
    for (int c = 0; c < CC; c++) {
        float4 d = __ldcs(&dp[((size_t)c) << 18]);
#pragma unroll
        for (int h = 0; h < HH; h++) {
            float w = Ws[h * CC + c];
            ax[h] += w * d.x; ay[h] += w * d.y; az[h] += w * d.z; aw[h] += w * d.w;
        }
    }

    int q  = p4 >> 8;          // row within S
    int k4 = p4 & 255;         // key quad
#pragma unroll
    for (int h = 0; h < HH; h++) {
        float fx = mk.x ? ax[h] : -60000.f;
        float fy = mk.y ? ay[h] : -60000.f;
        float fz = mk.z ? az[h] : -60000.f;
        float fw = mk.w ? aw[h] : -60000.f;
        char* rowb = reinterpret_cast<char*>(
            attn + (((size_t)(bb * HH + h) * SB + q)) * SB);
        uint2 st;
        st.x = packh2(fx, fy);
        st.y = packh2(fz, fw);
        *reinterpret_cast<uint2*>(rowb + 2048 + 8 * (size_t)k4) = st;
    }
}

// ---------------------------------------------------------------------------
// Kernel 2: fused attention, two-pass recompute, no score tile.
// grid = (b,h) x (S/128); 256 threads = 8 warps, warp w owns rows w*16..+15.
// Pass 1: stats (m,l) per row, online, registers only.
// Pass 2: recompute s (bit-identical), write attention, PV-accumulate O.
// smem = 18.4 KB -> 3 CTAs/SM.
// ---------------------------------------------------------------------------
__global__ __launch_bounds__(256, 3) void k_attn2(
    const float* __restrict__ Q, const float* __restrict__ K,
    const float* __restrict__ V, float* __restrict__ out)
{
    __shared__ unsigned Kbu[64 * KPU];
    __shared__ unsigned Vbu[64 * KPU];

    const int tid  = threadIdx.x;
    const int warp = tid >> 5;
    const int lane = tid & 31;
    const int g    = lane >> 2;
    const int tg   = lane & 3;

    const int bh = blockIdx.x >> 3;
    const int q0 = (blockIdx.x & 7) * 128;
    const int wb = warp * 16;

    const float* Qg = Q + ((size_t)bh * SB + q0 + wb) * DD;
    const float4* Kg4 = reinterpret_cast<const float4*>(K + (size_t)bh * SB * DD);
    const float4* Vg4 = reinterpret_cast<const float4*>(V + (size_t)bh * SB * DD);
    float* attnW = out + OUT_ELEMS + ((size_t)bh * SB + q0 + wb) * SB; // warp rows
    float* outW  = out + ((size_t)bh * SB + q0 + wb) * DD;

    // ---- Q fragments (rows wb+g, wb+g+8), scale 1/8 folded ----
    unsigned aq[4][4];
#pragma unroll
    for (int ks = 0; ks < 4; ks++) {
        float2 v0 = *reinterpret_cast<const float2*>(Qg + g * DD + ks * 16 + tg * 2);
        float2 v1 = *reinterpret_cast<const float2*>(Qg + (g + 8) * DD + ks * 16 + tg * 2);
        float2 v2 = *reinterpret_cast<const float2*>(Qg + g * DD + ks * 16 + 8 + tg * 2);
        float2 v3 = *reinterpret_cast<const float2*>(Qg + (g + 8) * DD + ks * 16 + 8 + tg * 2);
        aq[ks][0] = packh2(v0.x * 0.125f, v0.y * 0.125f);
        aq[ks][1] = packh2(v1.x * 0.125f, v1.y * 0.125f);
        aq[ks][2] = packh2(v2.x * 0.125f, v2.y * 0.125f);
        aq[ks][3] = packh2(v3.x * 0.125f, v3.y * 0.125f);
    }

    // ---- Pass 1: per-row (m, l) ----
    float m0 = -3.4e38f, m1 = -3.4e38f, l0 = 0.f, l1 = 0.f;

    for (int ch = 0; ch < 16; ++ch) {
        __syncthreads();
#pragma unroll
        for (int j = 0; j < 4; j++) {
            int i = tid + j * 256;
            int r = i >> 4, c = i & 15;
            float4 v = Kg4[(size_t)(ch * 64 + r) * 16 + c];
            Kbu[r * KPU + c * 2]     = packh2(v.x, v.y);
            Kbu[r * KPU + c * 2 + 1] = packh2(v.z, v.w);
        }
        __syncthreads();

#pragma unroll
        for (int t8 = 0; t8 < 8; t8++) {
            float c4[4] = {0.f, 0.f, 0.f, 0.f};
#pragma unroll
            for (int ks = 0; ks < 4; ks++) {
                unsigned b0 = Kbu[(t8 * 8 + g) * KPU + ks * 8 + tg];
                unsigned b1 = Kbu[(t8 * 8 + g) * KPU + ks * 8 + tg + 4];
                mma_f16(c4, aq[ks], b0, b1);
            }
            int n0 = ch * 64 + t8 * 8;
            const __half2* bp0 = reinterpret_cast<const __half2*>(
                reinterpret_cast<const char*>(attnW + (size_t)g * SB) + 2048 + (n0 + tg * 2) * 2);
            const __half2* bp1 = reinterpret_cast<const __half2*>(
                reinterpret_cast<const char*>(attnW + (size_t)(g + 8) * SB) + 2048 + (n0 + tg * 2) * 2);
            float2 b0f = __half22float2(*bp0);
            float2 b1f = __half22float2(*bp1);
            c4[0] += b0f.x; c4[1] += b0f.y; c4[2] += b1f.x; c4[3] += b1f.y;

            float t0 = fmaxf(c4[0], c4[1]);
            if (t0 > m0) { l0 *= __expf(m0 - t0); m0 = t0; }
            l0 += __expf(c4[0] - m0) + __expf(c4[1] - m0);
            float t1 = fmaxf(c4[2], c4[3]);
            if (t1 > m1) { l1 *= __expf(m1 - t1); m1 = t1; }
            l1 += __expf(c4[2] - m1) + __expf(c4[3] - m1);
        }
    }

    // quad reduce (m,l) across tg lanes
#pragma unroll
    for (int off = 1; off < 4; off <<= 1) {
        float mo = __shfl_xor_sync(0xffffffffu, m0, off);
        float lo = __shfl_xor_sync(0xffffffffu, l0, off);
        float mn = fmaxf(m0, mo);
        l0 = l0 * __expf(m0 - mn) + lo * __expf(mo - mn); m0 = mn;
        mo = __shfl_xor_sync(0xffffffffu, m1, off);
        lo = __shfl_xor_sync(0xffffffffu, l1, off);
        mn = fmaxf(m1, mo);
        l1 = l1 * __expf(m1 - mn) + lo * __expf(mo - mn); m1 = mn;
    }
    const float r0 = 1.f / l0, r1 = 1.f / l1;

    // ---- Pass 2: recompute s, write attention, accumulate O = P*V ----
    float oc[8][4];
#pragma unroll
    for (int dt = 0; dt < 8; dt++)
#pragma unroll
        for (int j = 0; j < 4; j++) oc[dt][j] = 0.f;

    __half* vh = reinterpret_cast<__half*>(Vbu);

    for (int ch = 0; ch < 16; ++ch) {
        __syncthreads();
#pragma unroll
        for (int j = 0; j < 4; j++) {
            int i = tid + j * 256;
            {   // K chunk (fp16, row = key)
                int r = i >> 4, c = i & 15;
                float4 v = Kg4[(size_t)(ch * 64 + r) * 16 + c];
                Kbu[r * KPU + c * 2]     = packh2(v.x, v.y);
                Kbu[r * KPU + c * 2 + 1] = packh2(v.z, v.w);
            }
            {   // V chunk transposed (Vt[dim][key])
                int r = i & 63, c = i >> 6;
                float4 v = Vg4[(size_t)(ch * 64 + r) * 16 + c];
                vh[(c * 4 + 0) * VPH + r] = __float2half_rn(v.x);
                vh[(c * 4 + 1) * VPH + r] = __float2half_rn(v.y);
                vh[(c * 4 + 2) * VPH + r] = __float2half_rn(v.z);
                vh[(c * 4 + 3) * VPH + r] = __float2half_rn(v.w);
            }
        }
        __syncthreads();

#pragma unroll
        for (int kg = 0; kg < 4; kg++) {          // 16-key groups
            unsigned ap[4];
#pragma unroll
            for (int hf = 0; hf < 2; hf++) {
                int t8 = kg * 2 + hf;
                float c4[4] = {0.f, 0.f, 0.f, 0.f};
#pragma unroll
                for (int ks = 0; ks < 4; ks++) {
                    unsigned b0 = Kbu[(t8 * 8 + g) * KPU + ks * 8 + tg];
                    unsigned b1 = Kbu[(t8 * 8 + g) * KPU + ks * 8 + tg + 4];
                    mma_f16(c4, aq[ks], b0, b1);
                }
                int n0 = ch * 64 + t8 * 8;
                const __half2* bp0 = reinterpret_cast<const __half2*>(
                    reinterpret_cast<const char*>(attnW + (size_t)g * SB) + 2048 + (n0 + tg * 2) * 2);
                const __half2* bp1 = reinterpret_cast<const __half2*>(
                    reinterpret_cast<const char*>(attnW + (size_t)(g + 8) * SB) + 2048 + (n0 + tg * 2) * 2);
                float2 b0f = __half22float2(*bp0);
                float2 b1f = __half22float2(*bp1);
                c4[0] += b0f.x; c4[1] += b0f.y; c4[2] += b1f.x; c4[3] += b1f.y;

                float p0 = __expf(c4[0] - m0) * r0;
                float p1 = __expf(c4[1] - m0) * r0;
                float p2 = __expf(c4[2] - m1) * r1;
                float p3 = __expf(c4[3] - m1) * r1;

                __stcs(reinterpret_cast<float2*>(attnW + (size_t)g * SB + n0 + tg * 2),
                       make_float2(p0, p1));
                __stcs(reinterpret_cast<float2*>(attnW + (size_t)(g + 8) * SB + n0 + tg * 2),
                       make_float2(p2, p3));

                ap[hf * 2]     = packh2(p0, p1);   // rows g   / g+8,
                ap[hf * 2 + 1] = packh2(p2, p3);   // keys lo (hf=0) / hi (hf=1)
            }
#pragma unroll
            for (int dt = 0; dt < 8; dt++) {
                unsigned b0 = Vbu[(dt * 8 + g) * KPU + kg * 8 + tg];
                unsigned b1 = Vbu[(dt * 8 + g) * KPU + kg * 8 + tg + 4];
                mma_f16(oc[dt], ap, b0, b1);
            }
        }
    }

    // ---- write O ----
#pragma unroll
    for (int dt = 0; dt < 8; dt++) {
        int col = dt * 8 + tg * 2;
        *reinterpret_cast<float2*>(outW + (size_t)g * DD + col) =
            make_float2(oc[dt][0], oc[dt][1]);
        *reinterpret_cast<float2*>(outW + (size_t)(g + 8) * DD + col) =
            make_float2(oc[dt][2], oc[dt][3]);
    }
}

// ---------------------------------------------------------------------------
extern "C" void kernel_launch(void* const* d_in, const int* in_sizes, int n_in,
                              void* d_out, int out_size)
{
    const float* Q    = (const float*)d_in[0];
    const float* K    = (const float*)d_in[1];
    const float* V    = (const float*)d_in[2];
    const float* dtw  = (const float*)d_in[3];
    const int*   mask = (const int*)d_in[4];
    const float* W    = (const float*)d_in[5];
    const float* bvec = (const float*)d_in[6];
    float*       out  = (float*)d_out;

    k_bias<<<(BB * SB * SB / 4) / 256, 256>>>(dtw, mask, W, bvec, out + OUT_ELEMS);
    k_attn2<<<BB * HH * (SB / 128), 256>>>(Q, K, V, out);
}